// round 1
// baseline (speedup 1.0000x reference)
#include <cuda_runtime.h>
#include <math.h>

// ---------------------------------------------------------------------------
// ExpertRouter: h = silu(x@W1+b1); logits = h@W2+b2;
// top-2 softmax weights + indices; Switch aux loss.
// Shapes: B=16384, D=4096, HID=2048, E=64, K=2.
// Output layout (float32): [weights B*2 | top_idx(as float) B*2 | aux_loss].
// ---------------------------------------------------------------------------

#define Bdim 16384
#define Ddim 4096
#define HIDd 2048
#define Ed   64

// scratch (device globals: allocation-free per harness rules)
__device__ float g_H[(size_t)Bdim * HIDd];      // 134 MB intermediate h
__device__ float g_pfreq[2048 * Ed];            // per-block freq partials
__device__ float g_pprob[2048 * Ed];            // per-block prob partials

// ---- packed f32x2 helpers (Blackwell FFMA2 pipe) ----
__device__ __forceinline__ unsigned long long pack2(float lo, float hi) {
    unsigned long long r;
    asm("mov.b64 %0, {%1, %2};" : "=l"(r) : "f"(lo), "f"(hi));
    return r;
}
__device__ __forceinline__ unsigned long long fma2(unsigned long long a,
                                                   unsigned long long b,
                                                   unsigned long long c) {
    unsigned long long d;
    asm("fma.rn.f32x2 %0, %1, %2, %3;" : "=l"(d) : "l"(a), "l"(b), "l"(c));
    return d;
}
__device__ __forceinline__ float2 unpack2(unsigned long long v) {
    float2 f;
    asm("mov.b64 {%0, %1}, %2;" : "=f"(f.x), "=f"(f.y) : "l"(v));
    return f;
}

__device__ __forceinline__ float silu_f(float v) {
    return v / (1.0f + expf(-v));
}

// ---------------------------------------------------------------------------
// Kernel 1: H = silu(x @ W1 + b1)
// 128x128x16 tile, 256 threads, 8x8 per-thread microtile, all math in f32x2.
// grid = (HID/128, B/128) = (16, 128)
// ---------------------------------------------------------------------------
#define BM 128
#define BN 128
#define BK 16

__global__ __launch_bounds__(256, 2)
void gemm1_silu(const float* __restrict__ x,
                const float* __restrict__ W1,
                const float* __restrict__ b1) {
    __shared__ float As[BK][BM];   // transposed A tile
    __shared__ float Bs[BK][BN];

    const int tid = threadIdx.x;
    const int rowBase = blockIdx.y * BM;
    const int colBase = blockIdx.x * BN;

    const int tm = (tid >> 4) * 8;   // 0..120
    const int tn = (tid & 15) * 8;   // 0..120

    // A-tile load mapping: 128 rows x 16 cols; 2 float4 per thread
    const int aRow = tid >> 1;           // 0..127
    const int aCol = (tid & 1) * 8;      // 0 or 8
    const float* xg = x + (size_t)(rowBase + aRow) * Ddim + aCol;

    // B-tile load mapping: 16 rows x 128 cols; 2 float4 per thread
    const int bRow = tid >> 4;           // 0..15
    const int bCol = (tid & 15) * 4;     // 0..60
    const float* wg = W1 + (size_t)bRow * HIDd + colBase + bCol;

    unsigned long long acc[8][4];
#pragma unroll
    for (int i = 0; i < 8; i++)
#pragma unroll
        for (int j = 0; j < 4; j++) acc[i][j] = 0ULL;

    for (int k0 = 0; k0 < Ddim; k0 += BK) {
        float4 a0 = *(const float4*)(xg + k0);
        float4 a1 = *(const float4*)(xg + k0 + 4);
        float4 w0 = *(const float4*)(wg + (size_t)k0 * HIDd);
        float4 w1 = *(const float4*)(wg + (size_t)k0 * HIDd + 64);

        __syncthreads();
        As[aCol + 0][aRow] = a0.x;
        As[aCol + 1][aRow] = a0.y;
        As[aCol + 2][aRow] = a0.z;
        As[aCol + 3][aRow] = a0.w;
        As[aCol + 4][aRow] = a1.x;
        As[aCol + 5][aRow] = a1.y;
        As[aCol + 6][aRow] = a1.z;
        As[aCol + 7][aRow] = a1.w;
        *(float4*)&Bs[bRow][bCol]      = w0;
        *(float4*)&Bs[bRow][bCol + 64] = w1;
        __syncthreads();

#pragma unroll
        for (int k = 0; k < BK; k++) {
            float4 av0 = *(const float4*)&As[k][tm];
            float4 av1 = *(const float4*)&As[k][tm + 4];
            float4 bv0 = *(const float4*)&Bs[k][tn];
            float4 bv1 = *(const float4*)&Bs[k][tn + 4];

            unsigned long long bp[4];
            bp[0] = pack2(bv0.x, bv0.y);
            bp[1] = pack2(bv0.z, bv0.w);
            bp[2] = pack2(bv1.x, bv1.y);
            bp[3] = pack2(bv1.z, bv1.w);

            float a[8] = {av0.x, av0.y, av0.z, av0.w, av1.x, av1.y, av1.z, av1.w};
#pragma unroll
            for (int i = 0; i < 8; i++) {
                unsigned long long ap = pack2(a[i], a[i]);
#pragma unroll
                for (int j = 0; j < 4; j++) acc[i][j] = fma2(ap, bp[j], acc[i][j]);
            }
        }
    }

    // epilogue: + b1, silu, store to g_H
#pragma unroll
    for (int i = 0; i < 8; i++) {
        const size_t gr = (size_t)(rowBase + tm + i);
#pragma unroll
        for (int j = 0; j < 4; j++) {
            float2 c = unpack2(acc[i][j]);
            int gc = colBase + tn + 2 * j;
            c.x = silu_f(c.x + b1[gc]);
            c.y = silu_f(c.y + b1[gc + 1]);
            *(float2*)&g_H[gr * HIDd + gc] = c;
        }
    }
}

// ---------------------------------------------------------------------------
// Kernel 2: logits = H @ W2 + b2; fused top-2 / softmax / partial stats.
// 8 rows per block (one warp per row), 256 threads, grid = B/8 = 2048.
// ---------------------------------------------------------------------------
__global__ __launch_bounds__(256)
void router_kernel(const float* __restrict__ W2,
                   const float* __restrict__ b2,
                   float* __restrict__ outW,
                   float* __restrict__ outI) {
    __shared__ float sW2[128][Ed];   // 32 KB
    __shared__ float sH[8][128];     // 4 KB
    __shared__ float sProb[8][Ed];   // 2 KB
    __shared__ int   sIdx1[8];

    const int tid  = threadIdx.x;
    const int warp = tid >> 5;
    const int lane = tid & 31;
    const int rowBase = blockIdx.x * 8;

    unsigned long long acc = 0ULL;

    for (int kc = 0; kc < HIDd; kc += 128) {
        __syncthreads();
        // W2 chunk: 128 x 64 floats = 2048 float4, 8 per thread
#pragma unroll
        for (int i = 0; i < 8; i++) {
            int idx = tid + 256 * i;          // 0..2047
            int r = idx >> 4, c4 = (idx & 15) * 4;
            *(float4*)&sW2[r][c4] =
                *(const float4*)&W2[(size_t)(kc + r) * Ed + c4];
        }
        // H chunk: 8 rows x 128 cols = 256 float4, 1 per thread
        {
            int r = tid >> 5, c = (tid & 31) * 4;
            *(float4*)&sH[r][c] =
                *(const float4*)&g_H[(size_t)(rowBase + r) * HIDd + kc + c];
        }
        __syncthreads();

#pragma unroll 4
        for (int k = 0; k < 128; k++) {
            float hv = sH[warp][k];
            unsigned long long hp = pack2(hv, hv);
            unsigned long long wv = *(const unsigned long long*)&sW2[k][lane * 2];
            acc = fma2(hp, wv, acc);
        }
    }

    float2 av = unpack2(acc);
    float l0 = av.x + b2[lane * 2];
    float l1 = av.y + b2[lane * 2 + 1];

    // local order (tie -> lower index, matching jax top_k/argmax)
    float bv, sv; int bi, si;
    if (l0 >= l1) { bv = l0; bi = lane * 2;     sv = l1; si = lane * 2 + 1; }
    else          { bv = l1; bi = lane * 2 + 1; sv = l0; si = lane * 2;     }

    // warp-reduce top1
    float v1 = bv; int i1 = bi;
#pragma unroll
    for (int off = 16; off; off >>= 1) {
        float ov = __shfl_down_sync(0xffffffffu, v1, off);
        int   oi = __shfl_down_sync(0xffffffffu, i1, off);
        if (ov > v1 || (ov == v1 && oi < i1)) { v1 = ov; i1 = oi; }
    }
    v1 = __shfl_sync(0xffffffffu, v1, 0);
    i1 = __shfl_sync(0xffffffffu, i1, 0);

    // candidate for second: exclude global top1 index
    float cv; int ci;
    if (bi == i1) { cv = sv; ci = si; } else { cv = bv; ci = bi; }
    float v2 = cv; int i2 = ci;
#pragma unroll
    for (int off = 16; off; off >>= 1) {
        float ov = __shfl_down_sync(0xffffffffu, v2, off);
        int   oi = __shfl_down_sync(0xffffffffu, i2, off);
        if (ov > v2 || (ov == v2 && oi < i2)) { v2 = ov; i2 = oi; }
    }
    v2 = __shfl_sync(0xffffffffu, v2, 0);
    i2 = __shfl_sync(0xffffffffu, i2, 0);

    // full-64 softmax (max == v1)
    float p0 = expf(l0 - v1);
    float p1 = expf(l1 - v1);
    float s = p0 + p1;
#pragma unroll
    for (int off = 16; off; off >>= 1) s += __shfl_down_sync(0xffffffffu, s, off);
    s = __shfl_sync(0xffffffffu, s, 0);
    float inv = 1.0f / s;
    sProb[warp][lane * 2]     = p0 * inv;
    sProb[warp][lane * 2 + 1] = p1 * inv;

    if (lane == 0) {
        sIdx1[warp] = i1;
        float d = expf(v2 - v1);                  // <= 1
        float w0 = 1.0f / (1.0f + d);
        float w1 = d / (1.0f + d);
        size_t gb = (size_t)(rowBase + warp);
        outW[gb * 2]     = w0;
        outW[gb * 2 + 1] = w1;
        outI[gb * 2]     = (float)i1;
        outI[gb * 2 + 1] = (float)i2;
    }
    __syncthreads();

    // deterministic per-block partials (fixed-order sums, no float atomics)
    if (tid < Ed) {
        float ps = 0.0f; int fc = 0;
#pragma unroll
        for (int r = 0; r < 8; r++) {
            ps += sProb[r][tid];
            fc += (sIdx1[r] == tid);
        }
        g_pprob[(size_t)blockIdx.x * Ed + tid] = ps;
        g_pfreq[(size_t)blockIdx.x * Ed + tid] = (float)fc;
    }
}

// ---------------------------------------------------------------------------
// Kernel 3: aux = E * sum_e (freq_e/B) * (avgprob_e/B), fixed-order reduction.
// ---------------------------------------------------------------------------
__global__ void aux_kernel(float* __restrict__ outAux) {
    __shared__ float red[Ed];
    const int e = threadIdx.x;    // 64 threads
    float f = 0.0f, p = 0.0f;
    for (int b = 0; b < 2048; b++) {
        f += g_pfreq[(size_t)b * Ed + e];
        p += g_pprob[(size_t)b * Ed + e];
    }
    red[e] = (f * (1.0f / (float)Bdim)) * (p * (1.0f / (float)Bdim));
    __syncthreads();
    if (e == 0) {
        float s = 0.0f;
        for (int i = 0; i < Ed; i++) s += red[i];
        outAux[0] = (float)Ed * s;
    }
}

// ---------------------------------------------------------------------------
extern "C" void kernel_launch(void* const* d_in, const int* in_sizes, int n_in,
                              void* d_out, int out_size) {
    const float* x  = (const float*)d_in[0];
    const float* W1 = (const float*)d_in[1];
    const float* b1 = (const float*)d_in[2];
    const float* W2 = (const float*)d_in[3];
    const float* b2 = (const float*)d_in[4];
    float* out = (float*)d_out;

    float* outW   = out;                 // [B,2] weights
    float* outI   = out + 2 * Bdim;      // [B,2] indices as float
    float* outAux = out + 4 * Bdim;      // scalar

    dim3 g1(HIDd / BN, Bdim / BM);       // (16, 128)
    gemm1_silu<<<g1, 256>>>(x, W1, b1);
    router_kernel<<<Bdim / 8, 256>>>(W2, b2, outW, outI);
    aux_kernel<<<1, Ed>>>(outAux);
}